// round 4
// baseline (speedup 1.0000x reference)
#include <cuda_runtime.h>

#define BATCH 16384

// ---------------- static scratch (device globals; no allocations) ----------------
__device__ float g_bufA[(long long)BATCH * 6000];
__device__ float g_bufB[(long long)BATCH * 3000];
__device__ float g_bufC[(long long)BATCH * 1875];
__device__ float g_x1 [(long long)BATCH * 2250];
__device__ float g_x2 [(long long)BATCH * 3750];

// Packed fp32x2 FMA (Blackwell FFMA2). d = a*b + d elementwise on 2 lanes.
__device__ __forceinline__ void ffma2(float2& d, const float2& a, const float2& b) {
    unsigned long long& dd = reinterpret_cast<unsigned long long&>(d);
    const unsigned long long& aa = reinterpret_cast<const unsigned long long&>(a);
    const unsigned long long& bb = reinterpret_cast<const unsigned long long&>(b);
    asm("fma.rn.f32x2 %0, %1, %2, %0;" : "+l"(dd) : "l"(aa), "l"(bb));
}

// ---------------- fully-templated GEMM, fused im2col / semi-linear gather --------
// f32x2 lanes pair adjacent M rows; B (weights) duplicated at staging.
// MODE 0: conv over H.  m=(b, oh*OW+ow), k=(ic*KH+kh). Output NCHW.
// MODE 1: semi-linear.  m=(b, r) r=(c*H+h), k over last axis. Output (...,N) = NCHW.
template<int MODE,int KH,int BM,int BN,int BK,int TM,int TN,int N,int K,
         int RELU,int ACCUM,int MINB,int NB>
__global__ void __launch_bounds__((BM/TM)*(BN/TN), MINB)
gemm(const float* __restrict__ A, const float* __restrict__ W,
     const float* __restrict__ bias, float* __restrict__ Out,
     int IH, int IW, int PH, int SP, int OW, int abstride)
{
    constexpr int NT    = (BM/TM)*(BN/TN);
    constexpr int KITER = (K + BK - 1) / BK;
    constexpr bool KG   = (K % BK) != 0;
    constexpr bool NG   = (N % BN) != 0;
    constexpr int ROWS  = (BM > NT) ? BM/NT : 1;
    constexpr int KSL   = (NT > BM) ? NT/BM : 1;
    constexpr int AJ    = BK / KSL;
    constexpr int BTOT  = BK * BN;
    constexpr int BITER = (BTOT + NT - 1) / NT;
    static_assert(BK % KSL == 0, "BK divisible by k-slot groups");
    static_assert(TM % 4 == 0, "TM mult of 4 (float4 A loads, M-pairs)");
    static_assert(TN % 2 == 0, "TN even (float4 B loads)");

    __shared__ __align__(16) float sA[BK][BM];
    __shared__ __align__(16) float sB[BK][2*BN + 4];

    const int tid = threadIdx.x;
    const int nb  = (int)(blockIdx.x % NB);
    const int mb  = (int)(blockIdx.x / NB);
    const int m0  = mb * BM;
    const int n0  = nb * BN;

    // ---- A row descriptors ----
    const int a_k0 = (NT > BM) ? (tid / BM) : 0;
    const float* Abase[ROWS];
    int oh_[ROWS], aml[ROWS];
    const int IHW = IH * IW;
#pragma unroll
    for (int r = 0; r < ROWS; r++) {
        const int ml = (NT >= BM) ? (tid % BM) : (tid + r * NT);
        aml[r] = ml;
        const int m = m0 + ml;
        const int b = m / SP;
        const int s = m - b * SP;
        if (MODE == 0) {
            const int oh = s / OW;
            oh_[r] = oh;
            Abase[r] = A + (long long)b * abstride + (s - oh * OW);
        } else {
            oh_[r] = 0;
            Abase[r] = A + (long long)b * abstride + (long long)s * K;
        }
    }

    const int tn = tid % (BN/TN);
    const int tm = tid / (BN/TN);

    float aReg[ROWS][AJ];
    float bReg[BITER];

    auto prefetch = [&](int kt) {
        const int k0 = kt * BK;
#pragma unroll
        for (int r = 0; r < ROWS; r++)
#pragma unroll
            for (int j = 0; j < AJ; j++) {
                const int k = k0 + a_k0 + KSL * j;
                float v = 0.0f;
                if (!KG || k < K) {
                    if (MODE == 0) {
                        const int ic = k / KH;
                        const int kh = k - ic * KH;
                        const int ih = oh_[r] + kh - PH;
                        if ((unsigned)ih < (unsigned)IH)
                            v = Abase[r][ic * IHW + ih * IW];
                    } else {
                        v = Abase[r][k];
                    }
                }
                aReg[r][j] = v;
            }
#pragma unroll
        for (int t = 0; t < BITER; t++) {
            const int idx = tid + t * NT;
            float v = 0.0f;
            if (BTOT % NT == 0 || idx < BTOT) {
                const int kl = idx % BK;
                const int n  = idx / BK;
                const int k  = k0 + kl;
                const int nn = n0 + n;
                if ((!KG || k < K) && (!NG || nn < N)) v = W[nn * K + k];
            }
            bReg[t] = v;
        }
    };

    auto stage = [&]() {
#pragma unroll
        for (int r = 0; r < ROWS; r++)
#pragma unroll
            for (int j = 0; j < AJ; j++)
                sA[a_k0 + KSL * j][aml[r]] = aReg[r][j];
#pragma unroll
        for (int t = 0; t < BITER; t++) {
            const int idx = tid + t * NT;
            if (BTOT % NT == 0 || idx < BTOT) {
                const int kl = idx % BK;
                const int n  = idx / BK;
                *(float2*)&sB[kl][2*n] = make_float2(bReg[t], bReg[t]);
            }
        }
    };

    float2 acc[TM/2][TN];
#pragma unroll
    for (int i = 0; i < TM/2; i++)
#pragma unroll
        for (int j = 0; j < TN; j++) acc[i][j] = make_float2(0.f, 0.f);

    prefetch(0);
    for (int kt = 0; kt < KITER; kt++) {
        stage();
        __syncthreads();
        if (kt + 1 < KITER) prefetch(kt + 1);
#pragma unroll
        for (int kk = 0; kk < BK; kk++) {
            float2 a2[TM/2], b2[TN];
            const float4* pa = (const float4*)&sA[kk][tm * TM];
#pragma unroll
            for (int q = 0; q < TM/4; q++) {
                const float4 t = pa[q];
                a2[2*q]   = make_float2(t.x, t.y);
                a2[2*q+1] = make_float2(t.z, t.w);
            }
            const float4* pb = (const float4*)&sB[kk][2 * tn * TN];
#pragma unroll
            for (int q = 0; q < TN/2; q++) {
                const float4 t = pb[q];
                b2[2*q]   = make_float2(t.x, t.y);   // (v,v)
                b2[2*q+1] = make_float2(t.z, t.w);   // (v',v')
            }
#pragma unroll
            for (int i = 0; i < TM/2; i++)
#pragma unroll
                for (int j = 0; j < TN; j++)
                    ffma2(acc[i][j], a2[i], b2[j]);
        }
        __syncthreads();
    }

    // ---- epilogue: bias (+relu) (+accumulate) ----
#pragma unroll
    for (int i = 0; i < TM/2; i++) {
#pragma unroll
        for (int h = 0; h < 2; h++) {
            const int m = m0 + tm * TM + 2*i + h;
            const int b = m / SP;
            const int s = m - b * SP;
#pragma unroll
            for (int j = 0; j < TN; j++) {
                const int n = n0 + tn * TN + j;
                if (!NG || n < N) {
                    float v = (h ? acc[i][j].y : acc[i][j].x) + bias[n];
                    if (RELU) v = fmaxf(v, 0.0f);
                    long long o;
                    if (MODE == 0) o = (long long)b * (N * SP) + (long long)n * SP + s;
                    else           o = (long long)b * (SP * N) + (long long)s * N + n;
                    if (ACCUM) Out[o] += v; else Out[o] = v;
                }
            }
        }
    }
}

// ---------------- host-side typed launchers ----------------
template<int KH,int BN,int BK,int TM,int TN,int N,int K,int ACCUM,int MINB>
static void conv(const float* A, const float* W, const float* b, float* O,
                 int IH, int IW, int PH)
{
    constexpr int BM = 128;
    constexpr int NB = (N + BN - 1) / BN;
    const int OH = IH + 2*PH - KH + 1, OW = IW, SP = OH * OW;
    const long long M = (long long)BATCH * SP;
    dim3 g((unsigned)((M / BM) * NB));
    gemm<0,KH,BM,BN,BK,TM,TN,N,K,0,ACCUM,MINB,NB><<<g, (BM/TM)*(BN/TN)>>>(
        A, W, b, O, IH, IW, PH, SP, OW, (K/KH)*IH*IW);
}

template<int BN,int BK,int TM,int TN,int N,int K,int RELU,int MINB>
static void sl(const float* A, const float* W, const float* b, float* O, int SP)
{
    constexpr int BM = 128;
    constexpr int NB = (N + BN - 1) / BN;
    const long long M = (long long)BATCH * SP;
    dim3 g((unsigned)((M / BM) * NB));
    gemm<1,1,BM,BN,BK,TM,TN,N,K,RELU,0,MINB,NB><<<g, (BM/TM)*(BN/TN)>>>(
        A, W, b, O, 1, 1, 0, SP, 1, SP*K);
}

extern "C" void kernel_launch(void* const* d_in, const int* in_sizes, int n_in,
                              void* d_out, int out_size)
{
    (void)in_sizes; (void)n_in; (void)out_size;
    const float* x    = (const float*)d_in[0];
    const float* w0a  = (const float*)d_in[1];  const float* b0a  = (const float*)d_in[2];
    const float* wl0  = (const float*)d_in[3];  const float* bl0  = (const float*)d_in[4];
    const float* w0b  = (const float*)d_in[5];  const float* b0b  = (const float*)d_in[6];
    const float* w0c  = (const float*)d_in[7];  const float* b0c  = (const float*)d_in[8];
    const float* wr0  = (const float*)d_in[9];  const float* br0  = (const float*)d_in[10];
    const float* w1   = (const float*)d_in[11]; const float* b1   = (const float*)d_in[12];
    const float* wl1  = (const float*)d_in[13]; const float* bl1  = (const float*)d_in[14];
    const float* w2   = (const float*)d_in[15]; const float* b2   = (const float*)d_in[16];
    const float* wa   = (const float*)d_in[17]; const float* ba   = (const float*)d_in[18];
    const float* wra  = (const float*)d_in[19]; const float* bra  = (const float*)d_in[20];
    const float* w0   = (const float*)d_in[21]; const float* b0   = (const float*)d_in[22];
    const float* wl2  = (const float*)d_in[23]; const float* bl2  = (const float*)d_in[24];
    const float* w0b2 = (const float*)d_in[25]; const float* b0b2 = (const float*)d_in[26];
    const float* w0c2 = (const float*)d_in[27]; const float* b0c2 = (const float*)d_in[28];
    const float* wr02 = (const float*)d_in[29]; const float* br02 = (const float*)d_in[30];
    float* out = (float*)d_out;

    float *A, *Bb, *C, *x1, *x2;
    cudaGetSymbolAddress((void**)&A,  g_bufA);
    cudaGetSymbolAddress((void**)&Bb, g_bufB);
    cudaGetSymbolAddress((void**)&C,  g_bufC);
    cudaGetSymbolAddress((void**)&x1, g_x1);
    cudaGetSymbolAddress((void**)&x2, g_x2);

    // ---- stage 0 ----
    conv<3,  8, 3, 8,2,   5,  3, 0, 8>(x,  w0a,  b0a,  A,  5, 27, 1); // (B,5,5,27)
    sl  <32, 9, 8,4,  18, 27, 1, 4   >(A,  wl0,  bl0,  Bb, 25);       // relu (B,5,5,18)
    conv<3, 32,15, 8,4,  25, 15, 0, 4>(Bb, w0b,  b0b,  x1, 5, 18, 1); // z -> x1
    sl  <32, 9, 8,4,  18, 27, 0, 4   >(x,  wr0,  br0,  C,  5);        // (B,1,5,18)
    conv<1, 32, 1, 8,4,  25,  1, 1, 4>(C,  w0c,  b0c,  x1, 5, 18, 0); // += y

    // ---- stage 1 ----
    conv<2, 16,10, 8,2,  75, 50, 0, 4>(x1, w1,   b1,   A,  5, 18, 0); // (B,75,4,18)
    sl  <16,18, 8,2,  10, 18, 1, 4   >(A,  wl1,  bl1,  Bb, 300);      // relu (B,75,4,10)
    conv<2, 64,16, 8,4, 125,150, 0, 3>(Bb, w2,   b2,   x2, 4, 10, 0); // z -> x2
    sl  <16,18, 8,2,  10, 18, 0, 4   >(x1, wra,  bra,  C,  125);      // (B,25,5,10)
    conv<3, 64,20, 8,4, 125, 75, 1, 3>(C,  wa,   ba,   x2, 5, 10, 0); // += y

    // ---- stage 2 ----
    conv<2, 64,16, 8,4, 300,250, 0, 3>(x2, w0,   b0,   A,  3, 10, 0); // (B,300,2,10)
    sl  < 8,10, 8,2,   5, 10, 1, 8   >(A,  wl2,  bl2,  Bb, 600);      // relu (B,300,2,5)
    conv<2, 64,20, 8,4, 512,600, 0, 3>(Bb, w0b2, b0b2, out, 2, 5, 0); // z -> out
    sl  < 8,10, 8,2,   5, 10, 0, 8   >(x2, wr02, br02, C,  375);      // (B,125,3,5)
    conv<3, 64,20, 8,4, 512,375, 1, 3>(C,  w0c2, b0c2, out, 3, 5, 0); // += y
}

// round 5
// speedup vs baseline: 1.7253x; 1.7253x over previous
#include <cuda_runtime.h>
#include <cuda_fp16.h>
#include <cstdint>

#define BATCH 16384

// ---------------- static scratch (device globals; no allocations) ----------------
__device__ float g_bufA[(long long)BATCH * 6000];
__device__ float g_bufB[(long long)BATCH * 3000];
__device__ float g_bufC[(long long)BATCH * 1875];
__device__ float g_x1 [(long long)BATCH * 2250];
__device__ float g_x2 [(long long)BATCH * 3750];

// Packed fp32x2 FMA (Blackwell FFMA2).
__device__ __forceinline__ void ffma2(float2& d, const float2& a, const float2& b) {
    unsigned long long& dd = reinterpret_cast<unsigned long long&>(d);
    const unsigned long long& aa = reinterpret_cast<const unsigned long long&>(a);
    const unsigned long long& bb = reinterpret_cast<const unsigned long long&>(b);
    asm("fma.rn.f32x2 %0, %1, %2, %0;" : "+l"(dd) : "l"(aa), "l"(bb));
}

// ============================================================================
// SIMT fp32 GEMM (R3 version, proven) — used for the 9 cheap layers
// ============================================================================
template<int MODE,int KH,int BM,int BN,int BK,int TM,int TN,int N,int K,int RELU,int ACCUM>
__global__ void __launch_bounds__((BM/TM)*(BN/TN), 2)
gemm(const float* __restrict__ A, const float* __restrict__ W,
     const float* __restrict__ bias, float* __restrict__ Out,
     int IH, int IW, int PH, int SP, int OW, int abstride)
{
    constexpr int NT    = (BM/TM)*(BN/TN);
    constexpr int KITER = (K + BK - 1) / BK;
    constexpr bool KG   = (K % BK) != 0;
    constexpr bool NG   = (N % BN) != 0;
    constexpr int ROWS  = (BM > NT) ? BM/NT : 1;
    constexpr int KSL   = (NT > BM) ? NT/BM : 1;
    constexpr int AJ    = BK / KSL;
    static_assert(BK % KSL == 0, "");
    static_assert(TN % 2 == 0, "");

    __shared__ __align__(16) float sA[BK][2*BM];
    __shared__ __align__(16) float sB[BK][BN + 4];

    const int tid = threadIdx.x;
    const int m0  = blockIdx.x * BM;
    const int n0  = blockIdx.y * BN;

    const int a_k0 = (NT > BM) ? (tid / BM) : 0;
    const float* Abase[ROWS];
    int oh_[ROWS], aml[ROWS];
    const int IHW = IH * IW;
#pragma unroll
    for (int r = 0; r < ROWS; r++) {
        const int ml = (NT >= BM) ? (tid % BM) : (tid + r * NT);
        aml[r] = ml;
        const int m = m0 + ml;
        const int b = m / SP;
        const int s = m - b * SP;
        if (MODE == 0) {
            const int oh = s / OW;
            oh_[r] = oh;
            Abase[r] = A + (long long)b * abstride + (s - oh * OW);
        } else {
            oh_[r] = 0;
            Abase[r] = A + (long long)b * abstride + (long long)s * K;
        }
    }

    const int tn = tid % (BN/TN);
    const int tm = tid / (BN/TN);

    float2 acc[TM][TN/2];
#pragma unroll
    for (int i = 0; i < TM; i++)
#pragma unroll
        for (int j = 0; j < TN/2; j++) acc[i][j] = make_float2(0.f, 0.f);

    for (int kt = 0; kt < KITER; kt++) {
        const int k0 = kt * BK;
#pragma unroll
        for (int r = 0; r < ROWS; r++) {
#pragma unroll
            for (int j = 0; j < AJ; j++) {
                const int kl = a_k0 + KSL * j;
                const int k  = k0 + kl;
                float v = 0.0f;
                if (!KG || k < K) {
                    if (MODE == 0) {
                        const int ic = k / KH;
                        const int kh = k - ic * KH;
                        const int ih = oh_[r] + kh - PH;
                        if ((unsigned)ih < (unsigned)IH)
                            v = Abase[r][ic * IHW + ih * IW];
                    } else {
                        v = Abase[r][k];
                    }
                }
                *(float2*)&sA[kl][2 * aml[r]] = make_float2(v, v);
            }
        }
        constexpr int BTOT = BK * BN;
        constexpr int BIT  = (BTOT + NT - 1) / NT;
#pragma unroll
        for (int t = 0; t < BIT; t++) {
            const int idx = tid + t * NT;
            if (BTOT % NT == 0 || idx < BTOT) {
                const int kl = idx % BK;
                const int n  = idx / BK;
                const int k  = k0 + kl;
                const int nn = n0 + n;
                float v = 0.0f;
                if ((!KG || k < K) && (!NG || nn < N)) v = W[nn * K + k];
                sB[kl][n] = v;
            }
        }
        __syncthreads();

#pragma unroll
        for (int kk = 0; kk < BK; kk++) {
            float2 a2[TM], b2[TN/2];
            {
                const float4* pa = (const float4*)&sA[kk][2 * tm * TM];
#pragma unroll
                for (int q = 0; q < TM/2; q++) {
                    const float4 t4 = pa[q];
                    a2[2*q]   = make_float2(t4.x, t4.y);
                    a2[2*q+1] = make_float2(t4.z, t4.w);
                }
            }
            if constexpr (TN % 4 == 0) {
                const float4* pb = (const float4*)&sB[kk][tn * TN];
#pragma unroll
                for (int q = 0; q < TN/4; q++) {
                    const float4 t4 = pb[q];
                    b2[2*q]   = make_float2(t4.x, t4.y);
                    b2[2*q+1] = make_float2(t4.z, t4.w);
                }
            } else {
                const float2* pb = (const float2*)&sB[kk][tn * TN];
#pragma unroll
                for (int q = 0; q < TN/2; q++) b2[q] = pb[q];
            }
#pragma unroll
            for (int i = 0; i < TM; i++)
#pragma unroll
                for (int j = 0; j < TN/2; j++)
                    ffma2(acc[i][j], a2[i], b2[j]);
        }
        __syncthreads();
    }

#pragma unroll
    for (int i = 0; i < TM; i++) {
        const int m = m0 + tm * TM + i;
        const int b = m / SP;
        const int s = m - b * SP;
#pragma unroll
        for (int j = 0; j < TN/2; j++) {
#pragma unroll
            for (int h = 0; h < 2; h++) {
                const int n = n0 + tn * TN + 2*j + h;
                if (!NG || n < N) {
                    float v = (h ? acc[i][j].y : acc[i][j].x) + bias[n];
                    if (RELU) v = fmaxf(v, 0.0f);
                    long long o;
                    if (MODE == 0) o = (long long)b * (N * SP) + (long long)n * SP + s;
                    else           o = (long long)b * (SP * N) + (long long)s * N + n;
                    if (ACCUM) Out[o] += v; else Out[o] = v;
                }
            }
        }
    }
}

// ============================================================================
// Tensor-core conv GEMM: fp16 mma.m16n8k16, fp32 accum, 3-MMA hi/lo split.
// CTA 128 thr, tile 64(M)x64(N)x32(K); warp tile 32x32.
// ============================================================================
__device__ __forceinline__ void mma16816(float* c, const uint32_t* a, const uint32_t* b) {
    asm volatile(
        "mma.sync.aligned.m16n8k16.row.col.f32.f16.f16.f32 "
        "{%0,%1,%2,%3}, {%4,%5,%6,%7}, {%8,%9}, {%0,%1,%2,%3};"
        : "+f"(c[0]), "+f"(c[1]), "+f"(c[2]), "+f"(c[3])
        : "r"(a[0]), "r"(a[1]), "r"(a[2]), "r"(a[3]), "r"(b[0]), "r"(b[1]));
}

template<int KH,int N,int K,int ACCUM,int NB>
__global__ void __launch_bounds__(128, 4)
tconv(const float* __restrict__ A, const float* __restrict__ W,
      const float* __restrict__ bias, float* __restrict__ Out,
      int IH, int IW, int PH, int SP, int OW, int abstride)
{
    constexpr int BM = 64, BN = 64, BK = 32;
    constexpr int KITER = (K + BK - 1) / BK;
    constexpr int PAD   = BK + 4;                 // half-stride: 36 halves = 72B
    __shared__ __align__(16) __half sAhi[BM][PAD];
    __shared__ __align__(16) __half sAlo[BM][PAD];
    __shared__ __align__(16) __half sBhi[BN][PAD];
    __shared__ __align__(16) __half sBlo[BN][PAD];

    const int tid  = threadIdx.x;
    const int nb   = (int)(blockIdx.x % NB);
    const int mb   = (int)(blockIdx.x / NB);
    const int m0   = mb * BM;
    const int n0   = nb * BN;
    const int IHW  = IH * IW;

    // ---- A row descriptor (fixed row per thread) ----
    const int arow = tid & 63;
    const int ak0  = tid >> 6;                    // 0/1; k slots ak0 + 2t
    {
        // nothing
    }
    const int am   = m0 + arow;
    const int ab   = am / SP;
    const int as   = am - ab * SP;
    const int aoh  = as / OW;
    const float* Abase = A + (long long)ab * abstride + (as - aoh * OW);

    // ---- B slot (fixed kl per thread) ----
    const int bkl = tid & 31;
    const int bn0 = tid >> 5;                     // n slots bn0 + 4t

    // warp/lane decomposition
    const int warp = tid >> 5, lane = tid & 31;
    const int wm = (warp & 1) * 32;               // warp m-offset within CTA tile
    const int wn = (warp >> 1) * 32;              // warp n-offset
    const int gr = lane >> 2;                     // 0..7
    const int gc = lane & 3;                      // 0..3

    float acc[2][4][4];
#pragma unroll
    for (int i = 0; i < 2; i++)
#pragma unroll
        for (int j = 0; j < 4; j++)
#pragma unroll
            for (int q = 0; q < 4; q++) acc[i][j][q] = 0.0f;

    for (int kt = 0; kt < KITER; kt++) {
        const int k0 = kt * BK;
        // ---- stage A (im2col gather, hi/lo split) ----
#pragma unroll
        for (int t = 0; t < 16; t++) {
            const int kl = ak0 + 2 * t;
            const int k  = k0 + kl;
            float v = 0.0f;
            if (K % BK == 0 || k < K) {
                const int ic = k / KH;
                const int kh = k - ic * KH;
                const int ih = aoh + kh - PH;
                if ((unsigned)ih < (unsigned)IH)
                    v = Abase[ic * IHW + ih * IW];
            }
            const __half hi = __float2half_rn(v);
            const __half lo = __float2half_rn(v - __half2float(hi));
            sAhi[arow][kl] = hi;
            sAlo[arow][kl] = lo;
        }
        // ---- stage B (weights, hi/lo split) ----
#pragma unroll
        for (int t = 0; t < 16; t++) {
            const int nl = bn0 + 4 * t;
            const int k  = k0 + bkl;
            const int nn = n0 + nl;
            float v = 0.0f;
            if ((K % BK == 0 || k < K) && (N % BN == 0 || nn < N))
                v = W[nn * K + k];
            const __half hi = __float2half_rn(v);
            const __half lo = __float2half_rn(v - __half2float(hi));
            sBhi[nl][bkl] = hi;
            sBlo[nl][bkl] = lo;
        }
        __syncthreads();

        // ---- compute: 2 k-chunks of 16 ----
#pragma unroll
        for (int ck = 0; ck < BK / 16; ck++) {
            const int kb = ck * 16 + 2 * gc;
            uint32_t ahi[2][4], alo[2][4], bhi[4][2], blo[4][2];
#pragma unroll
            for (int ms = 0; ms < 2; ms++) {
                const int r0 = wm + ms * 16 + gr;
                ahi[ms][0] = *(const uint32_t*)&sAhi[r0    ][kb    ];
                ahi[ms][1] = *(const uint32_t*)&sAhi[r0 + 8][kb    ];
                ahi[ms][2] = *(const uint32_t*)&sAhi[r0    ][kb + 8];
                ahi[ms][3] = *(const uint32_t*)&sAhi[r0 + 8][kb + 8];
                alo[ms][0] = *(const uint32_t*)&sAlo[r0    ][kb    ];
                alo[ms][1] = *(const uint32_t*)&sAlo[r0 + 8][kb    ];
                alo[ms][2] = *(const uint32_t*)&sAlo[r0    ][kb + 8];
                alo[ms][3] = *(const uint32_t*)&sAlo[r0 + 8][kb + 8];
            }
#pragma unroll
            for (int ns = 0; ns < 4; ns++) {
                const int nr = wn + ns * 8 + gr;
                bhi[ns][0] = *(const uint32_t*)&sBhi[nr][kb    ];
                bhi[ns][1] = *(const uint32_t*)&sBhi[nr][kb + 8];
                blo[ns][0] = *(const uint32_t*)&sBlo[nr][kb    ];
                blo[ns][1] = *(const uint32_t*)&sBlo[nr][kb + 8];
            }
#pragma unroll
            for (int ms = 0; ms < 2; ms++)
#pragma unroll
                for (int ns = 0; ns < 4; ns++) {
                    mma16816(acc[ms][ns], ahi[ms], bhi[ns]);
                    mma16816(acc[ms][ns], ahi[ms], blo[ns]);
                    mma16816(acc[ms][ns], alo[ms], bhi[ns]);
                }
        }
        __syncthreads();
    }

    // ---- epilogue: bias (+accumulate), NCHW scatter ----
#pragma unroll
    for (int ms = 0; ms < 2; ms++) {
        const int mr0 = m0 + wm + ms * 16 + gr;
#pragma unroll
        for (int half = 0; half < 2; half++) {
            const int m = mr0 + half * 8;
            const int b = m / SP;
            const int s = m - b * SP;
            const long long obase = (long long)b * (N * SP) + s;
#pragma unroll
            for (int ns = 0; ns < 4; ns++) {
                const int n = n0 + wn + ns * 8 + 2 * gc;
#pragma unroll
                for (int e = 0; e < 2; e++) {
                    const int nn = n + e;
                    if (N % BN == 0 || nn < N) {
                        const float v = acc[ms][ns][half * 2 + e] + bias[nn];
                        const long long o = obase + (long long)nn * SP;
                        if (ACCUM) Out[o] += v; else Out[o] = v;
                    }
                }
            }
        }
    }
}

// ---------------- host-side typed launchers ----------------
template<int KH,int BN,int BK,int TM,int TN,int N,int K,int ACCUM>
static void conv(const float* A, const float* W, const float* b, float* O,
                 int IH, int IW, int PH)
{
    constexpr int BM = 128;
    const int OH = IH + 2*PH - KH + 1, OW = IW, SP = OH * OW;
    const long long M = (long long)BATCH * SP;
    dim3 g((unsigned)(M / BM), (N + BN - 1) / BN);
    gemm<0,KH,BM,BN,BK,TM,TN,N,K,0,ACCUM><<<g, (BM/TM)*(BN/TN)>>>(
        A, W, b, O, IH, IW, PH, SP, OW, (K/KH)*IH*IW);
}

template<int KH,int N,int K,int ACCUM>
static void tconv_l(const float* A, const float* W, const float* b, float* O,
                    int IH, int IW, int PH)
{
    constexpr int NB = (N + 63) / 64;
    const int OH = IH + 2*PH - KH + 1, OW = IW, SP = OH * OW;
    const long long M = (long long)BATCH * SP;
    dim3 g((unsigned)((M / 64) * NB));
    tconv<KH,N,K,ACCUM,NB><<<g, 128>>>(A, W, b, O, IH, IW, PH, SP, OW, (K/KH)*IH*IW);
}

template<int BN,int BK,int TM,int TN,int N,int K,int RELU>
static void sl(const float* A, const float* W, const float* b, float* O, int SP)
{
    constexpr int BM = 128;
    const long long M = (long long)BATCH * SP;
    dim3 g((unsigned)(M / BM), (N + BN - 1) / BN);
    gemm<1,1,BM,BN,BK,TM,TN,N,K,RELU,0><<<g, (BM/TM)*(BN/TN)>>>(
        A, W, b, O, 1, 1, 0, SP, 1, SP*K);
}

extern "C" void kernel_launch(void* const* d_in, const int* in_sizes, int n_in,
                              void* d_out, int out_size)
{
    (void)in_sizes; (void)n_in; (void)out_size;
    const float* x    = (const float*)d_in[0];
    const float* w0a  = (const float*)d_in[1];  const float* b0a  = (const float*)d_in[2];
    const float* wl0  = (const float*)d_in[3];  const float* bl0  = (const float*)d_in[4];
    const float* w0b  = (const float*)d_in[5];  const float* b0b  = (const float*)d_in[6];
    const float* w0c  = (const float*)d_in[7];  const float* b0c  = (const float*)d_in[8];
    const float* wr0  = (const float*)d_in[9];  const float* br0  = (const float*)d_in[10];
    const float* w1   = (const float*)d_in[11]; const float* b1   = (const float*)d_in[12];
    const float* wl1  = (const float*)d_in[13]; const float* bl1  = (const float*)d_in[14];
    const float* w2   = (const float*)d_in[15]; const float* b2   = (const float*)d_in[16];
    const float* wa   = (const float*)d_in[17]; const float* ba   = (const float*)d_in[18];
    const float* wra  = (const float*)d_in[19]; const float* bra  = (const float*)d_in[20];
    const float* w0   = (const float*)d_in[21]; const float* b0   = (const float*)d_in[22];
    const float* wl2  = (const float*)d_in[23]; const float* bl2  = (const float*)d_in[24];
    const float* w0b2 = (const float*)d_in[25]; const float* b0b2 = (const float*)d_in[26];
    const float* w0c2 = (const float*)d_in[27]; const float* b0c2 = (const float*)d_in[28];
    const float* wr02 = (const float*)d_in[29]; const float* br02 = (const float*)d_in[30];
    float* out = (float*)d_out;

    float *A, *Bb, *C, *x1, *x2;
    cudaGetSymbolAddress((void**)&A,  g_bufA);
    cudaGetSymbolAddress((void**)&Bb, g_bufB);
    cudaGetSymbolAddress((void**)&C,  g_bufC);
    cudaGetSymbolAddress((void**)&x1, g_x1);
    cudaGetSymbolAddress((void**)&x2, g_x2);

    // ---- stage 0 (SIMT fp32, R3 configs) ----
    conv<3,  8, 4, 8,2,   5,  3, 0>(x,  w0a,  b0a,  A,  5, 27, 1); // (B,5,5,27)
    sl  <32, 9, 8,4,  18, 27, 1   >(A,  wl0,  bl0,  Bb, 25);       // relu (B,5,5,18)
    conv<3, 32,15, 8,4,  25, 15, 0>(Bb, w0b,  b0b,  x1, 5, 18, 1); // z -> x1
    sl  <32, 9, 8,4,  18, 27, 0   >(x,  wr0,  br0,  C,  5);        // (B,1,5,18)
    conv<1, 32, 1, 8,4,  25,  1, 1>(C,  w0c,  b0c,  x1, 5, 18, 0); // += y

    // ---- stage 1 ----
    tconv_l<2,  75,  50, 0>(x1, w1, b1, A, 5, 18, 0);              // (B,75,4,18)
    sl  <16, 6, 8,4,  10, 18, 1   >(A,  wl1,  bl1,  Bb, 300);      // relu (B,75,4,10)
    tconv_l<2, 125, 150, 0>(Bb, w2, b2, x2, 4, 10, 0);             // z -> x2 (B,125,3,10)
    sl  <16, 6, 8,4,  10, 18, 0   >(x1, wra,  bra,  C,  125);      // (B,25,5,10)
    tconv_l<3, 125,  75, 1>(C,  wa, ba, x2, 5, 10, 0);             // += y

    // ---- stage 2 ----
    tconv_l<2, 300, 250, 0>(x2, w0, b0, A, 3, 10, 0);              // (B,300,2,10)
    sl  < 8,10, 8,2,   5, 10, 1   >(A,  wl2,  bl2,  Bb, 600);      // relu (B,300,2,5)
    tconv_l<2, 512, 600, 0>(Bb, w0b2, b0b2, out, 2, 5, 0);         // z -> out
    sl  < 8,10, 8,2,   5, 10, 0   >(x2, wr02, br02, C,  375);      // (B,125,3,5)
    tconv_l<3, 512, 375, 1>(C,  w0c2, b0c2, out, 3, 5, 0);         // += y
}

// round 6
// speedup vs baseline: 1.8799x; 1.0896x over previous
#include <cuda_runtime.h>
#include <cuda_fp16.h>
#include <cstdint>

#define BATCH 16384

// ---------------- static scratch (device globals; no allocations) ----------------
__device__ float g_bufA[(long long)BATCH * 6000];
__device__ float g_bufB[(long long)BATCH * 3000];
__device__ float g_bufC[(long long)BATCH * 1875];
__device__ float g_x1 [(long long)BATCH * 2250];
__device__ float g_x2 [(long long)BATCH * 3750];
// half (hi,lo) interleaved planes for tensor-core consumers
__device__ __half2 g_hX[(long long)BATCH * 3750];   // x1 then x2
__device__ __half2 g_hB[(long long)BATCH * 3000];   // Bb (wl1 then wl2 outputs)
__device__ __half2 g_hC[(long long)BATCH * 1875];   // C  (wra then wr02 outputs)
__device__ __half2 g_hW[606080];                    // pre-split heavy weights

__device__ __forceinline__ __half2 split2(float v) {
    const __half hi = __float2half_rn(v);
    return __halves2half2(hi, __float2half_rn(v - __half2float(hi)));
}

// Packed fp32x2 FMA (Blackwell FFMA2).
__device__ __forceinline__ void ffma2(float2& d, const float2& a, const float2& b) {
    unsigned long long& dd = reinterpret_cast<unsigned long long&>(d);
    const unsigned long long& aa = reinterpret_cast<const unsigned long long&>(a);
    const unsigned long long& bb = reinterpret_cast<const unsigned long long&>(b);
    asm("fma.rn.f32x2 %0, %1, %2, %0;" : "+l"(dd) : "l"(aa), "l"(bb));
}

// ---------------- weight pre-split -------------------------------------------
__global__ void split_w(const float* __restrict__ w, __half2* __restrict__ o, int n) {
    const int i = blockIdx.x * 256 + threadIdx.x;
    if (i < n) o[i] = split2(w[i]);
}

// ============================================================================
// SIMT fp32 GEMM (R3 version, proven) + optional half-plane output
// ============================================================================
template<int MODE,int KH,int BM,int BN,int BK,int TM,int TN,int N,int K,int RELU,int ACCUM,int HOUT>
__global__ void __launch_bounds__((BM/TM)*(BN/TN), 2)
gemm(const float* __restrict__ A, const float* __restrict__ W,
     const float* __restrict__ bias, float* __restrict__ Out, __half2* __restrict__ hOut,
     int IH, int IW, int PH, int SP, int OW, int abstride)
{
    constexpr int NT    = (BM/TM)*(BN/TN);
    constexpr int KITER = (K + BK - 1) / BK;
    constexpr bool KG   = (K % BK) != 0;
    constexpr bool NG   = (N % BN) != 0;
    constexpr int ROWS  = (BM > NT) ? BM/NT : 1;
    constexpr int KSL   = (NT > BM) ? NT/BM : 1;
    constexpr int AJ    = BK / KSL;
    static_assert(BK % KSL == 0, "");
    static_assert(TN % 2 == 0, "");

    __shared__ __align__(16) float sA[BK][2*BM];
    __shared__ __align__(16) float sB[BK][BN + 4];

    const int tid = threadIdx.x;
    const int m0  = blockIdx.x * BM;
    const int n0  = blockIdx.y * BN;

    const int a_k0 = (NT > BM) ? (tid / BM) : 0;
    const float* Abase[ROWS];
    int oh_[ROWS], aml[ROWS];
    const int IHW = IH * IW;
#pragma unroll
    for (int r = 0; r < ROWS; r++) {
        const int ml = (NT >= BM) ? (tid % BM) : (tid + r * NT);
        aml[r] = ml;
        const int m = m0 + ml;
        const int b = m / SP;
        const int s = m - b * SP;
        if (MODE == 0) {
            const int oh = s / OW;
            oh_[r] = oh;
            Abase[r] = A + (long long)b * abstride + (s - oh * OW);
        } else {
            oh_[r] = 0;
            Abase[r] = A + (long long)b * abstride + (long long)s * K;
        }
    }

    const int tn = tid % (BN/TN);
    const int tm = tid / (BN/TN);

    float2 acc[TM][TN/2];
#pragma unroll
    for (int i = 0; i < TM; i++)
#pragma unroll
        for (int j = 0; j < TN/2; j++) acc[i][j] = make_float2(0.f, 0.f);

    for (int kt = 0; kt < KITER; kt++) {
        const int k0 = kt * BK;
#pragma unroll
        for (int r = 0; r < ROWS; r++) {
#pragma unroll
            for (int j = 0; j < AJ; j++) {
                const int kl = a_k0 + KSL * j;
                const int k  = k0 + kl;
                float v = 0.0f;
                if (!KG || k < K) {
                    if (MODE == 0) {
                        const int ic = k / KH;
                        const int kh = k - ic * KH;
                        const int ih = oh_[r] + kh - PH;
                        if ((unsigned)ih < (unsigned)IH)
                            v = Abase[r][ic * IHW + ih * IW];
                    } else {
                        v = Abase[r][k];
                    }
                }
                *(float2*)&sA[kl][2 * aml[r]] = make_float2(v, v);
            }
        }
        constexpr int BTOT = BK * BN;
        constexpr int BIT  = (BTOT + NT - 1) / NT;
#pragma unroll
        for (int t = 0; t < BIT; t++) {
            const int idx = tid + t * NT;
            if (BTOT % NT == 0 || idx < BTOT) {
                const int kl = idx % BK;
                const int n  = idx / BK;
                const int k  = k0 + kl;
                const int nn = n0 + n;
                float v = 0.0f;
                if ((!KG || k < K) && (!NG || nn < N)) v = W[nn * K + k];
                sB[kl][n] = v;
            }
        }
        __syncthreads();

#pragma unroll
        for (int kk = 0; kk < BK; kk++) {
            float2 a2[TM], b2[TN/2];
            {
                const float4* pa = (const float4*)&sA[kk][2 * tm * TM];
#pragma unroll
                for (int q = 0; q < TM/2; q++) {
                    const float4 t4 = pa[q];
                    a2[2*q]   = make_float2(t4.x, t4.y);
                    a2[2*q+1] = make_float2(t4.z, t4.w);
                }
            }
            if constexpr (TN % 4 == 0) {
                const float4* pb = (const float4*)&sB[kk][tn * TN];
#pragma unroll
                for (int q = 0; q < TN/4; q++) {
                    const float4 t4 = pb[q];
                    b2[2*q]   = make_float2(t4.x, t4.y);
                    b2[2*q+1] = make_float2(t4.z, t4.w);
                }
            } else {
                const float2* pb = (const float2*)&sB[kk][tn * TN];
#pragma unroll
                for (int q = 0; q < TN/2; q++) b2[q] = pb[q];
            }
#pragma unroll
            for (int i = 0; i < TM; i++)
#pragma unroll
                for (int j = 0; j < TN/2; j++)
                    ffma2(acc[i][j], a2[i], b2[j]);
        }
        __syncthreads();
    }

#pragma unroll
    for (int i = 0; i < TM; i++) {
        const int m = m0 + tm * TM + i;
        const int b = m / SP;
        const int s = m - b * SP;
#pragma unroll
        for (int j = 0; j < TN/2; j++) {
#pragma unroll
            for (int h = 0; h < 2; h++) {
                const int n = n0 + tn * TN + 2*j + h;
                if (!NG || n < N) {
                    float v = (h ? acc[i][j].y : acc[i][j].x) + bias[n];
                    if (RELU) v = fmaxf(v, 0.0f);
                    long long o;
                    if (MODE == 0) o = (long long)b * (N * SP) + (long long)n * SP + s;
                    else           o = (long long)b * (SP * N) + (long long)s * N + n;
                    if (ACCUM) v += Out[o];
                    Out[o] = v;
                    if (HOUT) hOut[o] = split2(v);
                }
            }
        }
    }
}

// ============================================================================
// Tensor-core conv GEMM v2: pre-split (hi,lo) half2 inputs, reg prefetch.
// CTA 128 thr, tile 64(M)x64(N)x32(K); warp tile 32x32; 3-MMA hi/lo split.
// ============================================================================
__device__ __forceinline__ void mma16816(float* c, const uint32_t* a, const uint32_t* b) {
    asm volatile(
        "mma.sync.aligned.m16n8k16.row.col.f32.f16.f16.f32 "
        "{%0,%1,%2,%3}, {%4,%5,%6,%7}, {%8,%9}, {%0,%1,%2,%3};"
        : "+f"(c[0]), "+f"(c[1]), "+f"(c[2]), "+f"(c[3])
        : "r"(a[0]), "r"(a[1]), "r"(a[2]), "r"(a[3]), "r"(b[0]), "r"(b[1]));
}

template<int KH,int N,int K,int ACCUM,int HOUT,int NB>
__global__ void __launch_bounds__(128, 4)
tconv(const __half2* __restrict__ Ah, const __half2* __restrict__ Wh,
      const float* __restrict__ bias, float* __restrict__ Out, __half2* __restrict__ hOut,
      int IH, int IW, int PH, int SP, int OW, int abstride)
{
    constexpr int BM = 64, BN = 64, BK = 32;
    constexpr int KITER = (K + BK - 1) / BK;
    constexpr int PAD   = 38;                      // 76B row stride: conflict-free
    __shared__ __align__(16) __half sAhi[BM][PAD];
    __shared__ __align__(16) __half sAlo[BM][PAD];
    __shared__ __align__(16) __half sBhi[BN][PAD];
    __shared__ __align__(16) __half sBlo[BN][PAD];

    const int tid  = threadIdx.x;
    const int nb   = (int)(blockIdx.x % NB);
    const int mb   = (int)(blockIdx.x / NB);
    const int m0   = mb * BM;
    const int n0   = nb * BN;
    const int IHW  = IH * IW;

    // ---- A row descriptor (fixed row per thread) ----
    const int arow = tid & 63;
    const int ak0  = tid >> 6;                    // 0/1; k slots ak0 + 2t
    const int am   = m0 + arow;
    const int ab   = am / SP;
    const int as   = am - ab * SP;
    const int aoh  = as / OW;
    const __half2* Abase = Ah + (long long)ab * abstride + (as - aoh * OW);

    // ---- B slot (fixed kl per thread) ----
    const int bkl = tid & 31;
    const int bn0 = tid >> 5;                     // n slots bn0 + 4t

    const int warp = tid >> 5, lane = tid & 31;
    const int wm = (warp & 1) * 32;
    const int wn = (warp >> 1) * 32;
    const int gr = lane >> 2;
    const int gc = lane & 3;

    __half2 aR[16], bR[16];
    const __half2 Z2 = __float2half2_rn(0.0f);

    auto prefetch = [&](int kt) {
        const int k0 = kt * BK;
#pragma unroll
        for (int t = 0; t < 16; t++) {
            const int k = k0 + ak0 + 2 * t;
            __half2 v = Z2;
            if (K % BK == 0 || k < K) {
                const int ic = k / KH;
                const int kh = k - ic * KH;
                const int ih = aoh + kh - PH;
                if ((unsigned)ih < (unsigned)IH)
                    v = Abase[ic * IHW + ih * IW];
            }
            aR[t] = v;
        }
        const int kB = k0 + bkl;
#pragma unroll
        for (int t = 0; t < 16; t++) {
            const int nn = n0 + bn0 + 4 * t;
            __half2 v = Z2;
            if ((K % BK == 0 || kB < K) && (N % BN == 0 || nn < N))
                v = Wh[(long long)nn * K + kB];
            bR[t] = v;
        }
    };

    auto stage = [&]() {
#pragma unroll
        for (int t = 0; t < 16; t++) {
            const int kl = ak0 + 2 * t;
            sAhi[arow][kl] = __low2half(aR[t]);
            sAlo[arow][kl] = __high2half(aR[t]);
        }
#pragma unroll
        for (int t = 0; t < 16; t++) {
            const int nl = bn0 + 4 * t;
            sBhi[nl][bkl] = __low2half(bR[t]);
            sBlo[nl][bkl] = __high2half(bR[t]);
        }
    };

    float acc[2][4][4];
#pragma unroll
    for (int i = 0; i < 2; i++)
#pragma unroll
        for (int j = 0; j < 4; j++)
#pragma unroll
            for (int q = 0; q < 4; q++) acc[i][j][q] = 0.0f;

    prefetch(0);
    for (int kt = 0; kt < KITER; kt++) {
        stage();
        __syncthreads();
        if (kt + 1 < KITER) prefetch(kt + 1);
#pragma unroll
        for (int ck = 0; ck < BK / 16; ck++) {
            const int kb = ck * 16 + 2 * gc;
            uint32_t ahi[2][4], alo[2][4], bhi[4][2], blo[4][2];
#pragma unroll
            for (int ms = 0; ms < 2; ms++) {
                const int r0 = wm + ms * 16 + gr;
                ahi[ms][0] = *(const uint32_t*)&sAhi[r0    ][kb    ];
                ahi[ms][1] = *(const uint32_t*)&sAhi[r0 + 8][kb    ];
                ahi[ms][2] = *(const uint32_t*)&sAhi[r0    ][kb + 8];
                ahi[ms][3] = *(const uint32_t*)&sAhi[r0 + 8][kb + 8];
                alo[ms][0] = *(const uint32_t*)&sAlo[r0    ][kb    ];
                alo[ms][1] = *(const uint32_t*)&sAlo[r0 + 8][kb    ];
                alo[ms][2] = *(const uint32_t*)&sAlo[r0    ][kb + 8];
                alo[ms][3] = *(const uint32_t*)&sAlo[r0 + 8][kb + 8];
            }
#pragma unroll
            for (int ns = 0; ns < 4; ns++) {
                const int nr = wn + ns * 8 + gr;
                bhi[ns][0] = *(const uint32_t*)&sBhi[nr][kb    ];
                bhi[ns][1] = *(const uint32_t*)&sBhi[nr][kb + 8];
                blo[ns][0] = *(const uint32_t*)&sBlo[nr][kb    ];
                blo[ns][1] = *(const uint32_t*)&sBlo[nr][kb + 8];
            }
#pragma unroll
            for (int ms = 0; ms < 2; ms++)
#pragma unroll
                for (int ns = 0; ns < 4; ns++) {
                    mma16816(acc[ms][ns], ahi[ms], bhi[ns]);
                    mma16816(acc[ms][ns], ahi[ms], blo[ns]);
                    mma16816(acc[ms][ns], alo[ms], bhi[ns]);
                }
        }
        __syncthreads();
    }

    // ---- epilogue: bias (+accumulate) (+half planes), NCHW scatter ----
#pragma unroll
    for (int ms = 0; ms < 2; ms++) {
        const int mr0 = m0 + wm + ms * 16 + gr;
#pragma unroll
        for (int half = 0; half < 2; half++) {
            const int m = mr0 + half * 8;
            const int b = m / SP;
            const int s = m - b * SP;
            const long long obase = (long long)b * (N * SP) + s;
#pragma unroll
            for (int ns = 0; ns < 4; ns++) {
                const int n = n0 + wn + ns * 8 + 2 * gc;
#pragma unroll
                for (int e = 0; e < 2; e++) {
                    const int nn = n + e;
                    if (N % BN == 0 || nn < N) {
                        float v = acc[ms][ns][half * 2 + e] + bias[nn];
                        const long long o = obase + (long long)nn * SP;
                        if (ACCUM) v += Out[o];
                        Out[o] = v;
                        if (HOUT) hOut[o] = split2(v);
                    }
                }
            }
        }
    }
}

// ---------------- host-side typed launchers ----------------
template<int KH,int BN,int BK,int TM,int TN,int N,int K,int ACCUM,int HOUT>
static void conv(const float* A, const float* W, const float* b, float* O, __half2* hO,
                 int IH, int IW, int PH)
{
    constexpr int BM = 128;
    const int OH = IH + 2*PH - KH + 1, OW = IW, SP = OH * OW;
    const long long M = (long long)BATCH * SP;
    dim3 g((unsigned)(M / BM), (N + BN - 1) / BN);
    gemm<0,KH,BM,BN,BK,TM,TN,N,K,0,ACCUM,HOUT><<<g, (BM/TM)*(BN/TN)>>>(
        A, W, b, O, hO, IH, IW, PH, SP, OW, (K/KH)*IH*IW);
}

template<int KH,int N,int K,int ACCUM,int HOUT>
static void tconv_l(const __half2* A, const __half2* W, const float* b, float* O,
                    __half2* hO, int IH, int IW, int PH)
{
    constexpr int NB = (N + 63) / 64;
    const int OH = IH + 2*PH - KH + 1, OW = IW, SP = OH * OW;
    const long long M = (long long)BATCH * SP;
    dim3 g((unsigned)((M / 64) * NB));
    tconv<KH,N,K,ACCUM,HOUT,NB><<<g, 128>>>(A, W, b, O, hO, IH, IW, PH, SP, OW, (K/KH)*IH*IW);
}

template<int BN,int BK,int TM,int TN,int N,int K,int RELU,int HOUT>
static void sl(const float* A, const float* W, const float* b, float* O, __half2* hO, int SP)
{
    constexpr int BM = 128;
    const long long M = (long long)BATCH * SP;
    dim3 g((unsigned)(M / BM), (N + BN - 1) / BN);
    gemm<1,1,BM,BN,BK,TM,TN,N,K,RELU,0,HOUT><<<g, (BM/TM)*(BN/TN)>>>(
        A, W, b, O, hO, 1, 1, 0, SP, 1, SP*K);
}

extern "C" void kernel_launch(void* const* d_in, const int* in_sizes, int n_in,
                              void* d_out, int out_size)
{
    (void)in_sizes; (void)n_in; (void)out_size;
    const float* x    = (const float*)d_in[0];
    const float* w0a  = (const float*)d_in[1];  const float* b0a  = (const float*)d_in[2];
    const float* wl0  = (const float*)d_in[3];  const float* bl0  = (const float*)d_in[4];
    const float* w0b  = (const float*)d_in[5];  const float* b0b  = (const float*)d_in[6];
    const float* w0c  = (const float*)d_in[7];  const float* b0c  = (const float*)d_in[8];
    const float* wr0  = (const float*)d_in[9];  const float* br0  = (const float*)d_in[10];
    const float* w1   = (const float*)d_in[11]; const float* b1   = (const float*)d_in[12];
    const float* wl1  = (const float*)d_in[13]; const float* bl1  = (const float*)d_in[14];
    const float* w2   = (const float*)d_in[15]; const float* b2   = (const float*)d_in[16];
    const float* wa   = (const float*)d_in[17]; const float* ba   = (const float*)d_in[18];
    const float* wra  = (const float*)d_in[19]; const float* bra  = (const float*)d_in[20];
    const float* w0   = (const float*)d_in[21]; const float* b0   = (const float*)d_in[22];
    const float* wl2  = (const float*)d_in[23]; const float* bl2  = (const float*)d_in[24];
    const float* w0b2 = (const float*)d_in[25]; const float* b0b2 = (const float*)d_in[26];
    const float* w0c2 = (const float*)d_in[27]; const float* b0c2 = (const float*)d_in[28];
    const float* wr02 = (const float*)d_in[29]; const float* br02 = (const float*)d_in[30];
    float* out = (float*)d_out;

    float *A, *Bb, *C, *x1, *x2;
    __half2 *hX, *hB, *hC, *hW;
    cudaGetSymbolAddress((void**)&A,  g_bufA);
    cudaGetSymbolAddress((void**)&Bb, g_bufB);
    cudaGetSymbolAddress((void**)&C,  g_bufC);
    cudaGetSymbolAddress((void**)&x1, g_x1);
    cudaGetSymbolAddress((void**)&x2, g_x2);
    cudaGetSymbolAddress((void**)&hX, g_hX);
    cudaGetSymbolAddress((void**)&hB, g_hB);
    cudaGetSymbolAddress((void**)&hC, g_hC);
    cudaGetSymbolAddress((void**)&hW, g_hW);

    // ---- weight pre-split (hi,lo) for the 6 heavy layers ----
    __half2* hw1   = hW;            // 3750
    __half2* hw2   = hW + 3750;     // 18750
    __half2* hwa   = hW + 22500;    // 9375
    __half2* hw0   = hW + 31875;    // 75000
    __half2* hw0b2 = hW + 106875;   // 307200
    __half2* hw0c2 = hW + 414075;   // 192000
    split_w<<<(3750+255)/256,   256>>>(w1,   hw1,   3750);
    split_w<<<(18750+255)/256,  256>>>(w2,   hw2,   18750);
    split_w<<<(9375+255)/256,   256>>>(wa,   hwa,   9375);
    split_w<<<(75000+255)/256,  256>>>(w0,   hw0,   75000);
    split_w<<<(307200+255)/256, 256>>>(w0b2, hw0b2, 307200);
    split_w<<<(192000+255)/256, 256>>>(w0c2, hw0c2, 192000);

    // ---- stage 0 (SIMT fp32, R3 configs) ----
    conv<3,  8, 4, 8,2,   5,  3, 0,0>(x,  w0a,  b0a,  A,  nullptr, 5, 27, 1);
    sl  <32, 9, 8,4,  18, 27, 1, 0  >(A,  wl0,  bl0,  Bb, nullptr, 25);
    conv<3, 32,15, 8,4,  25, 15, 0,0>(Bb, w0b,  b0b,  x1, nullptr, 5, 18, 1);
    sl  <32, 9, 8,4,  18, 27, 0, 0  >(x,  wr0,  br0,  C,  nullptr, 5);
    conv<1, 32, 1, 8,4,  25,  1, 1,1>(C,  w0c,  b0c,  x1, hX,      5, 18, 0); // final x1 + half

    // ---- stage 1 ----
    tconv_l<2,  75,  50, 0,0>(hX, hw1, b1, A, nullptr, 5, 18, 0);   // (B,75,4,18)
    sl  <16, 6, 8,4,  10, 18, 1, 1  >(A,  wl1,  bl1,  Bb, hB, 300); // relu + half
    tconv_l<2, 125, 150, 0,0>(hB, hw2, b2, x2, nullptr, 4, 10, 0);  // z -> x2
    sl  <16, 6, 8,4,  10, 18, 0, 1  >(x1, wra,  bra,  C,  hC, 125); // + half
    tconv_l<3, 125,  75, 1,1>(hC, hwa, ba, x2, hX, 5, 10, 0);       // += y, final x2 + half

    // ---- stage 2 ----
    tconv_l<2, 300, 250, 0,0>(hX, hw0, b0, A, nullptr, 3, 10, 0);   // (B,300,2,10)
    sl  < 8,10, 8,2,   5, 10, 1, 1  >(A,  wl2,  bl2,  Bb, hB, 600); // relu + half
    tconv_l<2, 512, 600, 0,0>(hB, hw0b2, b0b2, out, nullptr, 2, 5, 0);
    sl  < 8,10, 8,2,   5, 10, 0, 1  >(x2, wr02, br02, C,  hC, 375); // + half
    tconv_l<3, 512, 375, 1,0>(hC, hw0c2, b0c2, out, nullptr, 3, 5, 0);
}